// round 1
// baseline (speedup 1.0000x reference)
#include <cuda_runtime.h>
#include <cstdint>

// Problem constants
#define Bb 32
#define Vv 5
#define Nn 196
#define Cc 768
#define Hh 768
#define BN_ROWS (Bb * Nn)        // 6272
#define BVN (Bb * Vv * Nn)       // 31360
#define NUM_ITERS 3

// ---------------------------------------------------------------------------
// Scratch (device globals; no runtime allocation allowed)
// ---------------------------------------------------------------------------
__device__ float g_P[(size_t)BVN * Cc];      // proj_x  [B,V,N,C]   96 MB
__device__ float g_XW1[(size_t)BVN * Hh];    // x @ w1[:C]          96 MB
__device__ float g_C[(size_t)BN_ROWS * Cc];  // c       [B,N,C]     19 MB
__device__ float g_CW1[(size_t)BN_ROWS * Hh];// c @ w1[C:]          19 MB
__device__ float g_S[BVN];                   // scores s

// ---------------------------------------------------------------------------
// Mean over views: c0[b,n,:] = mean_v x[b,v,n,:]
// ---------------------------------------------------------------------------
__global__ void mean_kernel(const float* __restrict__ x, float* __restrict__ c) {
    int i = blockIdx.x * blockDim.x + threadIdx.x;      // over BN_ROWS * C/4
    const int TOT = BN_ROWS * (Cc / 4);
    if (i >= TOT) return;
    int bn = i / (Cc / 4);
    int cq = (i % (Cc / 4)) * 4;
    int b = bn / Nn, n = bn % Nn;
    float4 acc = make_float4(0.f, 0.f, 0.f, 0.f);
#pragma unroll
    for (int v = 0; v < Vv; v++) {
        const float4 xv = *(const float4*)(x + ((size_t)((b * Vv + v) * Nn + n)) * Cc + cq);
        acc.x += xv.x; acc.y += xv.y; acc.z += xv.z; acc.w += xv.w;
    }
    const float s = 1.0f / Vv;
    acc.x *= s; acc.y *= s; acc.z *= s; acc.w *= s;
    *(float4*)(c + (size_t)bn * Cc + cq) = acc;
}

// ---------------------------------------------------------------------------
// Tiled SGEMM: Cout[M,768] = A[M,768] @ Bw[768,768]  (all row-major, exact tiles)
// BM=BN=128, BK=8, TM=TN=8, 256 threads.
// ---------------------------------------------------------------------------
#define BM 128
#define BNt 128
#define BKt 8
#define TM 8
#define TN 8

__global__ __launch_bounds__(256, 2)
void sgemm_rm(const float* __restrict__ A, const float* __restrict__ Bw,
              float* __restrict__ Cout) {
    __shared__ float As[BKt][BM];
    __shared__ float Bs[BKt][BNt];
    const int K = 768, Nc = 768;
    int tid = threadIdx.x;
    int cRow = blockIdx.y, cCol = blockIdx.x;

    int tCol = tid % 16;
    int tRow = tid / 16;
    int aRow = tid / 2;
    int aCol = (tid % 2) * 4;
    int bRow = tid / 32;
    int bCol = (tid % 32) * 4;

    const float* Aptr = A + ((size_t)cRow * BM + aRow) * K;
    const float* Bptr = Bw + (size_t)bRow * Nc + (size_t)cCol * BNt + bCol;

    float acc[TM][TN];
#pragma unroll
    for (int i = 0; i < TM; i++)
#pragma unroll
        for (int j = 0; j < TN; j++) acc[i][j] = 0.f;

    for (int k0 = 0; k0 < K; k0 += BKt) {
        float4 av = *(const float4*)(Aptr + k0 + aCol);
        As[aCol + 0][aRow] = av.x;
        As[aCol + 1][aRow] = av.y;
        As[aCol + 2][aRow] = av.z;
        As[aCol + 3][aRow] = av.w;
        *(float4*)&Bs[bRow][bCol] = *(const float4*)(Bptr + (size_t)k0 * Nc);
        __syncthreads();
#pragma unroll
        for (int k = 0; k < BKt; k++) {
            float regM[TM], regN[TN];
            *(float4*)&regM[0] = *(const float4*)&As[k][tRow * TM];
            *(float4*)&regM[4] = *(const float4*)&As[k][tRow * TM + 4];
            *(float4*)&regN[0] = *(const float4*)&Bs[k][tCol * TN];
            *(float4*)&regN[4] = *(const float4*)&Bs[k][tCol * TN + 4];
#pragma unroll
            for (int i = 0; i < TM; i++)
#pragma unroll
                for (int j = 0; j < TN; j++) acc[i][j] += regM[i] * regN[j];
        }
        __syncthreads();
    }
#pragma unroll
    for (int i = 0; i < TM; i++) {
        float* crow = Cout + ((size_t)cRow * BM + tRow * TM + i) * Nc + (size_t)cCol * BNt + tCol * TN;
        *(float4*)(crow)     = *(float4*)&acc[i][0];
        *(float4*)(crow + 4) = *(float4*)&acc[i][4];
    }
}

// ---------------------------------------------------------------------------
// Per-view projection GEMM: P[b,v,n,:] = x[b,v,n,:] @ w_views[v]
// Row index within a tile maps (b,n) -> gathered x row for view v=blockIdx.z.
// ---------------------------------------------------------------------------
__global__ __launch_bounds__(256, 2)
void sgemm_proj(const float* __restrict__ X, const float* __restrict__ Wviews,
                float* __restrict__ P) {
    __shared__ float As[BKt][BM];
    __shared__ float Bs[BKt][BNt];
    const int K = 768, Nc = 768;
    int tid = threadIdx.x;
    int cRow = blockIdx.y, cCol = blockIdx.x;
    int v = blockIdx.z;
    const float* Bw = Wviews + (size_t)v * K * Nc;

    int tCol = tid % 16;
    int tRow = tid / 16;
    int aRow = tid / 2;
    int aCol = (tid % 2) * 4;
    int bRow = tid / 32;
    int bCol = (tid % 32) * 4;

    int gRowA = cRow * BM + aRow;          // row over (b,n)
    int ab = gRowA / Nn, an = gRowA % Nn;
    const float* Aptr = X + ((size_t)((ab * Vv + v) * Nn + an)) * K;
    const float* Bptr = Bw + (size_t)bRow * Nc + (size_t)cCol * BNt + bCol;

    float acc[TM][TN];
#pragma unroll
    for (int i = 0; i < TM; i++)
#pragma unroll
        for (int j = 0; j < TN; j++) acc[i][j] = 0.f;

    for (int k0 = 0; k0 < K; k0 += BKt) {
        float4 av = *(const float4*)(Aptr + k0 + aCol);
        As[aCol + 0][aRow] = av.x;
        As[aCol + 1][aRow] = av.y;
        As[aCol + 2][aRow] = av.z;
        As[aCol + 3][aRow] = av.w;
        *(float4*)&Bs[bRow][bCol] = *(const float4*)(Bptr + (size_t)k0 * Nc);
        __syncthreads();
#pragma unroll
        for (int k = 0; k < BKt; k++) {
            float regM[TM], regN[TN];
            *(float4*)&regM[0] = *(const float4*)&As[k][tRow * TM];
            *(float4*)&regM[4] = *(const float4*)&As[k][tRow * TM + 4];
            *(float4*)&regN[0] = *(const float4*)&Bs[k][tCol * TN];
            *(float4*)&regN[4] = *(const float4*)&Bs[k][tCol * TN + 4];
#pragma unroll
            for (int i = 0; i < TM; i++)
#pragma unroll
                for (int j = 0; j < TN; j++) acc[i][j] += regM[i] * regN[j];
        }
        __syncthreads();
    }
#pragma unroll
    for (int i = 0; i < TM; i++) {
        int gor = cRow * BM + tRow * TM + i;
        int ob = gor / Nn, on = gor % Nn;
        float* crow = P + ((size_t)((ob * Vv + v) * Nn + on)) * Nc + (size_t)cCol * BNt + tCol * TN;
        *(float4*)(crow)     = *(float4*)&acc[i][0];
        *(float4*)(crow + 4) = *(float4*)&acc[i][4];
    }
}

// ---------------------------------------------------------------------------
// Score kernel: one warp per (b,v,n) row.
// s = dot(tanh(XW1_row + CW1_row + b1), w2) + b2
// ---------------------------------------------------------------------------
__global__ void score_kernel(const float* __restrict__ XW1, const float* __restrict__ CW1,
                             const float* __restrict__ b1, const float* __restrict__ w2,
                             const float* __restrict__ b2, float* __restrict__ S) {
    int gwarp = (blockIdx.x * blockDim.x + threadIdx.x) >> 5;
    int lane = threadIdx.x & 31;
    if (gwarp >= BVN) return;
    int b = gwarp / (Vv * Nn);
    int rem = gwarp % (Vv * Nn);
    int n = rem % Nn;
    const float* xr = XW1 + (size_t)gwarp * Hh;
    const float* cr = CW1 + (size_t)(b * Nn + n) * Hh;
    float sum = 0.f;
#pragma unroll
    for (int h = lane * 4; h < Hh; h += 128) {
        float4 xv = *(const float4*)(xr + h);
        float4 cv = *(const float4*)(cr + h);
        float4 bb = *(const float4*)(b1 + h);
        float4 wv = *(const float4*)(w2 + h);
        sum += tanhf(xv.x + cv.x + bb.x) * wv.x;
        sum += tanhf(xv.y + cv.y + bb.y) * wv.y;
        sum += tanhf(xv.z + cv.z + bb.z) * wv.z;
        sum += tanhf(xv.w + cv.w + bb.w) * wv.w;
    }
#pragma unroll
    for (int off = 16; off; off >>= 1) sum += __shfl_xor_sync(0xFFFFFFFFu, sum, off);
    if (lane == 0) S[gwarp] = sum + b2[0];
}

// ---------------------------------------------------------------------------
// Softmax over views + weighted-sum update. Optionally emits r (last iter).
// One block (192 threads) per (b,n); thread t handles channels [4t, 4t+4).
// ---------------------------------------------------------------------------
__global__ void update_kernel(const float* __restrict__ S, const float* __restrict__ P,
                              float* __restrict__ Cnew, float* __restrict__ Rout) {
    int bn = blockIdx.x;
    int b = bn / Nn, n = bn % Nn;
    float sv[Vv];
    float mx = -1e30f;
#pragma unroll
    for (int v = 0; v < Vv; v++) {
        sv[v] = S[(size_t)(b * Vv + v) * Nn + n];
        mx = fmaxf(mx, sv[v]);
    }
    float den = 0.f;
#pragma unroll
    for (int v = 0; v < Vv; v++) { sv[v] = expf(sv[v] - mx); den += sv[v]; }
    float inv = 1.0f / den;
#pragma unroll
    for (int v = 0; v < Vv; v++) sv[v] *= inv;

    int ch = threadIdx.x * 4;
    float4 acc = make_float4(0.f, 0.f, 0.f, 0.f);
#pragma unroll
    for (int v = 0; v < Vv; v++) {
        const float4 pv = *(const float4*)(P + ((size_t)((b * Vv + v) * Nn + n)) * Cc + ch);
        acc.x += sv[v] * pv.x; acc.y += sv[v] * pv.y;
        acc.z += sv[v] * pv.z; acc.w += sv[v] * pv.w;
    }
    *(float4*)(Cnew + (size_t)bn * Cc + ch) = acc;

    if (Rout != nullptr && threadIdx.x == 0) {
        float ent = 0.f;
#pragma unroll
        for (int v = 0; v < Vv; v++) ent -= sv[v] * logf(sv[v] + 1e-8f);
        Rout[bn] = 1.0f - ent / logf((float)Vv);
    }
}

// ---------------------------------------------------------------------------
// Launch
// ---------------------------------------------------------------------------
extern "C" void kernel_launch(void* const* d_in, const int* in_sizes, int n_in,
                              void* d_out, int out_size) {
    const float* x       = (const float*)d_in[0];  // [B,V,N,C]
    const float* w_views = (const float*)d_in[1];  // [V,C,C]
    const float* w1      = (const float*)d_in[2];  // [2C,H]
    const float* b1      = (const float*)d_in[3];  // [H]
    const float* w2      = (const float*)d_in[4];  // [H,1]
    const float* b2      = (const float*)d_in[5];  // [1]
    float* out = (float*)d_out;                    // c [B,N,C] then r [B,N]

    float *P, *XW1, *Cbuf, *CW1, *S;
    cudaGetSymbolAddress((void**)&P,    g_P);
    cudaGetSymbolAddress((void**)&XW1,  g_XW1);
    cudaGetSymbolAddress((void**)&Cbuf, g_C);
    cudaGetSymbolAddress((void**)&CW1,  g_CW1);
    cudaGetSymbolAddress((void**)&S,    g_S);

    // 1) c0 = mean over views
    {
        int tot = BN_ROWS * (Cc / 4);
        mean_kernel<<<(tot + 255) / 256, 256>>>(x, Cbuf);
    }
    // 2) proj_x = x @ w_views (per view)
    {
        dim3 grid(768 / BNt, BN_ROWS / BM, Vv);   // (6, 49, 5)
        sgemm_proj<<<grid, 256>>>(x, w_views, P);
    }
    // 3) XW1 = x @ w1[:C]   (x flattened is row-major [BVN, C])
    {
        dim3 grid(768 / BNt, BVN / BM);           // (6, 245)
        sgemm_rm<<<grid, 256>>>(x, w1, XW1);
    }
    // 4) iterations
    const float* w1b = w1 + (size_t)Cc * Hh;      // rows C..2C-1
    for (int it = 0; it < NUM_ITERS; it++) {
        dim3 gridc(768 / BNt, BN_ROWS / BM);      // (6, 49)
        sgemm_rm<<<gridc, 256>>>(Cbuf, w1b, CW1);

        int nwarps = BVN;
        int blocks = (nwarps * 32 + 255) / 256;
        score_kernel<<<blocks, 256>>>(XW1, CW1, b1, w2, b2, S);

        bool last = (it == NUM_ITERS - 1);
        float* cdst = last ? out : Cbuf;
        float* rdst = last ? (out + (size_t)BN_ROWS * Cc) : nullptr;
        update_kernel<<<BN_ROWS, 192>>>(S, P, cdst, rdst);
    }
    (void)in_sizes; (void)n_in; (void)out_size;
}

// round 3
// speedup vs baseline: 1.8566x; 1.8566x over previous
#include <cuda_runtime.h>
#include <cuda_bf16.h>
#include <cstdint>

#define Bb 32
#define Vv 5
#define Nn 196
#define Cc 768
#define Hh 768
#define BN_ROWS 6272            // Bb*Nn
#define BVN 31360               // Bb*Vv*Nn
#define NUM_ITERS 3
#define WMAT (Cc*Cc)            // 589824

// ---------------------------------------------------------------------------
// Scratch (device globals; no runtime allocation allowed)
// ---------------------------------------------------------------------------
__device__ float g_P[(size_t)BVN * Cc];        // proj_x   fp32
__device__ float g_XW1[(size_t)BVN * Hh];      // x @ w1[:C]
__device__ float g_CW1[(size_t)BN_ROWS * Hh];  // c @ w1[C:]
__device__ float g_S[BVN];                     // scores
__device__ __nv_bfloat16 g_xh[(size_t)BVN * Cc];
__device__ __nv_bfloat16 g_xl[(size_t)BVN * Cc];
__device__ __nv_bfloat16 g_ch[(size_t)BN_ROWS * Cc];
__device__ __nv_bfloat16 g_cl[(size_t)BN_ROWS * Cc];
// 7 transposed [N,K] weight matrices: views 0..4, w1a=5, w1b=6
__device__ __nv_bfloat16 g_Wh[(size_t)7 * WMAT];
__device__ __nv_bfloat16 g_Wl[(size_t)7 * WMAT];

// ---------------------------------------------------------------------------
// Helpers
// ---------------------------------------------------------------------------
__device__ __forceinline__ uint32_t su32(const void* p) {
    uint32_t a;
    asm("{ .reg .u64 t; cvta.to.shared.u64 t, %1; cvt.u32.u64 %0, t; }" : "=r"(a) : "l"(p));
    return a;
}
__device__ __forceinline__ void cpa16(uint32_t d, const void* s) {
    asm volatile("cp.async.cg.shared.global [%0], [%1], 16;" :: "r"(d), "l"(s) : "memory");
}
__device__ __forceinline__ void cp_commit() {
    asm volatile("cp.async.commit_group;" ::: "memory");
}
__device__ __forceinline__ void ldsm4(uint32_t& r0, uint32_t& r1, uint32_t& r2, uint32_t& r3,
                                      uint32_t addr) {
    asm volatile("ldmatrix.sync.aligned.m8n8.x4.shared.b16 {%0,%1,%2,%3}, [%4];"
                 : "=r"(r0), "=r"(r1), "=r"(r2), "=r"(r3) : "r"(addr));
}
__device__ __forceinline__ void mma16816(float* d, const uint32_t* a, const uint32_t* b) {
    asm volatile(
        "mma.sync.aligned.m16n8k16.row.col.f32.bf16.bf16.f32 "
        "{%0,%1,%2,%3}, {%4,%5,%6,%7}, {%8,%9}, {%0,%1,%2,%3};"
        : "+f"(d[0]), "+f"(d[1]), "+f"(d[2]), "+f"(d[3])
        : "r"(a[0]), "r"(a[1]), "r"(a[2]), "r"(a[3]), "r"(b[0]), "r"(b[1]));
}

__device__ __forceinline__ void split1(float a, uint16_t& h, uint16_t& l) {
    __nv_bfloat16 bh = __float2bfloat16(a);
    __nv_bfloat16 bl = __float2bfloat16(a - __bfloat162float(bh));
    h = *(uint16_t*)&bh;
    l = *(uint16_t*)&bl;
}

// ---------------------------------------------------------------------------
// Split x into bf16 hi/lo
// ---------------------------------------------------------------------------
__global__ void split_x_kernel(const float* __restrict__ x) {
    size_t i = (size_t)blockIdx.x * blockDim.x + threadIdx.x;
    const size_t TOT = (size_t)BVN * Cc / 4;
    if (i >= TOT) return;
    float4 v = *(const float4*)(x + i * 4);
    union { uint16_t u[4]; uint2 p; } hh, ll;
    split1(v.x, hh.u[0], ll.u[0]);
    split1(v.y, hh.u[1], ll.u[1]);
    split1(v.z, hh.u[2], ll.u[2]);
    split1(v.w, hh.u[3], ll.u[3]);
    *(uint2*)(g_xh + i * 4) = hh.p;
    *(uint2*)(g_xl + i * 4) = ll.p;
}

// ---------------------------------------------------------------------------
// Transpose + split weights into g_Wh/g_Wl ([N,K] K-major, 7 matrices)
// ---------------------------------------------------------------------------
__global__ void split_w_kernel(const float* __restrict__ w_views, const float* __restrict__ w1) {
    size_t j = (size_t)blockIdx.x * blockDim.x + threadIdx.x;
    const size_t TOT = (size_t)7 * WMAT;
    if (j >= TOT) return;
    int m = (int)(j / WMAT);
    int r = (int)(j % WMAT);
    int n = r / Cc, k = r % Cc;
    float s;
    if (m < 5)       s = w_views[(size_t)m * WMAT + (size_t)k * Cc + n];
    else if (m == 5) s = w1[(size_t)k * Hh + n];
    else             s = w1[(size_t)(Cc + k) * Hh + n];
    uint16_t h, l;
    split1(s, h, l);
    *(uint16_t*)(g_Wh + j) = h;
    *(uint16_t*)(g_Wl + j) = l;
}

// ---------------------------------------------------------------------------
// Mean over views -> c0 as bf16 hi/lo
// ---------------------------------------------------------------------------
__global__ void mean_kernel(const float* __restrict__ x) {
    int i = blockIdx.x * blockDim.x + threadIdx.x;
    const int TOT = BN_ROWS * (Cc / 4);
    if (i >= TOT) return;
    int bn = i / (Cc / 4);
    int cq = (i % (Cc / 4)) * 4;
    int b = bn / Nn, n = bn % Nn;
    float4 acc = make_float4(0.f, 0.f, 0.f, 0.f);
#pragma unroll
    for (int v = 0; v < Vv; v++) {
        const float4 xv = *(const float4*)(x + ((size_t)((b * Vv + v) * Nn + n)) * Cc + cq);
        acc.x += xv.x; acc.y += xv.y; acc.z += xv.z; acc.w += xv.w;
    }
    const float s = 1.0f / Vv;
    acc.x *= s; acc.y *= s; acc.z *= s; acc.w *= s;
    union { uint16_t u[4]; uint2 p; } hh, ll;
    split1(acc.x, hh.u[0], ll.u[0]);
    split1(acc.y, hh.u[1], ll.u[1]);
    split1(acc.z, hh.u[2], ll.u[2]);
    split1(acc.w, hh.u[3], ll.u[3]);
    size_t o = (size_t)bn * Cc + cq;
    *(uint2*)(g_ch + o) = hh.p;
    *(uint2*)(g_cl + o) = ll.p;
}

// ---------------------------------------------------------------------------
// mma.sync bf16x3 GEMM: Cout[M,768], CTA tile 128x128, K=768 in 12 chunks of 64.
// 8 warps (2M x 4N), warp tile 64x32. SW128 xor swizzle, cp.async double buffer.
// MODE 0: flat rows. MODE 1: per-view gather/scatter (v = blockIdx.z), B offset
//         by v*WMAT.
// ---------------------------------------------------------------------------
#define STAGE_BYTES 65536          // 4 tiles x 16KB (Ah, Al, Bh, Bl)
#define SMEM_TOTAL  (2 * STAGE_BYTES)
#define OFF_AL 16384
#define OFF_BH 32768
#define OFF_BL 49152

template <int MODE>
__global__ __launch_bounds__(256, 1)
void mma_gemm(const __nv_bfloat16* __restrict__ Ah, const __nv_bfloat16* __restrict__ Al,
              const __nv_bfloat16* __restrict__ Bh, const __nv_bfloat16* __restrict__ Bl,
              float* __restrict__ Cout) {
    extern __shared__ char smem[];
    const uint32_t sb = su32(smem);
    const int tid = threadIdx.x;
    const int lane = tid & 31;
    const int wid = tid >> 5;
    const int warpM = wid & 1;
    const int warpN = wid >> 1;
    const int MBase = blockIdx.y * 128;
    const int NBase = blockIdx.x * 128;
    const int v = blockIdx.z;

    if (MODE == 1) { Bh += (size_t)v * WMAT; Bl += (size_t)v * WMAT; }

    // ---- load geometry: each thread owns one tile-row half (64B) ----
    const int lr = tid >> 1;                 // tile row 0..127
    const int lc = (tid & 1) * 64;           // byte offset within 128B row
    int gaRow;
    if (MODE == 1) {
        int bn = MBase + lr;
        int b = bn / Nn, n = bn - b * Nn;
        gaRow = (b * Vv + v) * Nn + n;
    } else {
        gaRow = MBase + lr;
    }
    const char* aRowPtr = (const char*)(Ah + (size_t)gaRow * Cc) + lc;
    const char* bRowPtr = (const char*)(Bh + (size_t)(NBase + lr) * Cc) + lc;
    const ptrdiff_t dAl = (const char*)Al - (const char*)Ah;
    const ptrdiff_t dBl = (const char*)Bl - (const char*)Bh;
    uint32_t so[4];
#pragma unroll
    for (int j = 0; j < 4; j++)
        so[j] = (uint32_t)(lr * 128 + ((lc + j * 16) ^ ((lr & 7) << 4)));

    auto issue = [&](int chunk, int stg) {
        uint32_t base = sb + stg * STAGE_BYTES;
        const char* pa = aRowPtr + chunk * 128;
        const char* pb = bRowPtr + chunk * 128;
#pragma unroll
        for (int j = 0; j < 4; j++) {
            cpa16(base + so[j], pa + j * 16);
            cpa16(base + OFF_AL + so[j], pa + dAl + j * 16);
            cpa16(base + OFF_BH + so[j], pb + j * 16);
            cpa16(base + OFF_BL + so[j], pb + dBl + j * 16);
        }
        cp_commit();
    };

    float acc[4][4][4];
#pragma unroll
    for (int mt = 0; mt < 4; mt++)
#pragma unroll
        for (int nt = 0; nt < 4; nt++)
#pragma unroll
            for (int e = 0; e < 4; e++) acc[mt][nt][e] = 0.f;

    // ldmatrix per-thread addressing (within-tile), swizzle xor = (lane&7)<<4
    const uint32_t swz = (uint32_t)((lane & 7) << 4);
    const uint32_t aRow0 = (uint32_t)(warpM * 64 + (lane & 15));
    const uint32_t nRow0 = (uint32_t)(warpN * 32 + (lane & 15));
    const uint32_t halfSel = (uint32_t)((lane >> 4) << 4);   // 0 or 16 bytes

    issue(0, 0);
#pragma unroll 1
    for (int i = 0; i < 12; i++) {
        int stg = i & 1;
        if (i + 1 < 12) {
            issue(i + 1, stg ^ 1);
            asm volatile("cp.async.wait_group 1;" ::: "memory");
        } else {
            asm volatile("cp.async.wait_group 0;" ::: "memory");
        }
        __syncthreads();

        uint32_t base = sb + stg * STAGE_BYTES;
#pragma unroll
        for (int k16 = 0; k16 < 4; k16++) {
            const uint32_t bc = (uint32_t)(k16 * 32) + halfSel;
            uint32_t ah[4][4], al[4][4], bh[4][2], bl[4][2];
#pragma unroll
            for (int mt = 0; mt < 4; mt++) {
                uint32_t row = aRow0 + mt * 16;
                uint32_t ad = base + row * 128 + (bc ^ swz);
                ldsm4(ah[mt][0], ah[mt][1], ah[mt][2], ah[mt][3], ad);
                ldsm4(al[mt][0], al[mt][1], al[mt][2], al[mt][3], ad + OFF_AL);
            }
#pragma unroll
            for (int g = 0; g < 2; g++) {
                uint32_t row = nRow0 + g * 16;
                uint32_t ad = base + OFF_BH + row * 128 + (bc ^ swz);
                uint32_t r0, r1, r2, r3;
                ldsm4(r0, r1, r2, r3, ad);
                bh[g * 2 + 0][0] = r0; bh[g * 2 + 0][1] = r2;
                bh[g * 2 + 1][0] = r1; bh[g * 2 + 1][1] = r3;
                ldsm4(r0, r1, r2, r3, ad + (OFF_BL - OFF_BH));
                bl[g * 2 + 0][0] = r0; bl[g * 2 + 0][1] = r2;
                bl[g * 2 + 1][0] = r1; bl[g * 2 + 1][1] = r3;
            }
#pragma unroll
            for (int mt = 0; mt < 4; mt++)
#pragma unroll
                for (int nt = 0; nt < 4; nt++) {
                    mma16816(acc[mt][nt], ah[mt], bh[nt]);
                    mma16816(acc[mt][nt], ah[mt], bl[nt]);
                    mma16816(acc[mt][nt], al[mt], bh[nt]);
                }
        }
        __syncthreads();
    }

    // ---- epilogue ----
    int grow[8];
#pragma unroll
    for (int mt = 0; mt < 4; mt++) {
#pragma unroll
        for (int h = 0; h < 2; h++) {
            int m = MBase + warpM * 64 + mt * 16 + (lane >> 2) + h * 8;
            if (MODE == 1) {
                int b = m / Nn, n = m - b * Nn;
                grow[mt * 2 + h] = (b * Vv + v) * Nn + n;
            } else {
                grow[mt * 2 + h] = m;
            }
        }
    }
    const int ncol0 = NBase + warpN * 32 + (lane & 3) * 2;
#pragma unroll
    for (int mt = 0; mt < 4; mt++)
#pragma unroll
        for (int nt = 0; nt < 4; nt++) {
            float* p0 = Cout + (size_t)grow[mt * 2 + 0] * Cc + ncol0 + nt * 8;
            float* p1 = Cout + (size_t)grow[mt * 2 + 1] * Cc + ncol0 + nt * 8;
            p0[0] = acc[mt][nt][0]; p0[1] = acc[mt][nt][1];
            p1[0] = acc[mt][nt][2]; p1[1] = acc[mt][nt][3];
        }
}

// ---------------------------------------------------------------------------
// Score: one warp per (b,v,n) row. s = dot(tanh(XW1+CW1+b1), w2) + b2
// ---------------------------------------------------------------------------
__global__ void score_kernel(const float* __restrict__ XW1, const float* __restrict__ CW1,
                             const float* __restrict__ b1, const float* __restrict__ w2,
                             const float* __restrict__ b2, float* __restrict__ S) {
    int gwarp = (blockIdx.x * blockDim.x + threadIdx.x) >> 5;
    int lane = threadIdx.x & 31;
    if (gwarp >= BVN) return;
    int b = gwarp / (Vv * Nn);
    int rem = gwarp % (Vv * Nn);
    int n = rem % Nn;
    const float* xr = XW1 + (size_t)gwarp * Hh;
    const float* cr = CW1 + (size_t)(b * Nn + n) * Hh;
    float sum = 0.f;
#pragma unroll
    for (int h = lane * 4; h < Hh; h += 128) {
        float4 xv = *(const float4*)(xr + h);
        float4 cv = *(const float4*)(cr + h);
        float4 bb = *(const float4*)(b1 + h);
        float4 wv = *(const float4*)(w2 + h);
        sum += tanhf(xv.x + cv.x + bb.x) * wv.x;
        sum += tanhf(xv.y + cv.y + bb.y) * wv.y;
        sum += tanhf(xv.z + cv.z + bb.z) * wv.z;
        sum += tanhf(xv.w + cv.w + bb.w) * wv.w;
    }
#pragma unroll
    for (int off = 16; off; off >>= 1) sum += __shfl_xor_sync(0xFFFFFFFFu, sum, off);
    if (lane == 0) S[gwarp] = sum + b2[0];
}

// ---------------------------------------------------------------------------
// Softmax over views + weighted-sum update.
// Non-last iters: write c as bf16 hi/lo. Last iter: write fp32 c + r.
// ---------------------------------------------------------------------------
__global__ void update_kernel(const float* __restrict__ S, const float* __restrict__ P,
                              float* __restrict__ OutC, float* __restrict__ Rout, int last) {
    int bn = blockIdx.x;
    int b = bn / Nn, n = bn % Nn;
    float sv[Vv];
    float mx = -1e30f;
#pragma unroll
    for (int v = 0; v < Vv; v++) {
        sv[v] = S[(size_t)(b * Vv + v) * Nn + n];
        mx = fmaxf(mx, sv[v]);
    }
    float den = 0.f;
#pragma unroll
    for (int v = 0; v < Vv; v++) { sv[v] = expf(sv[v] - mx); den += sv[v]; }
    float inv = 1.0f / den;
#pragma unroll
    for (int v = 0; v < Vv; v++) sv[v] *= inv;

    int ch = threadIdx.x * 4;
    float4 acc = make_float4(0.f, 0.f, 0.f, 0.f);
#pragma unroll
    for (int v = 0; v < Vv; v++) {
        const float4 pv = *(const float4*)(P + ((size_t)((b * Vv + v) * Nn + n)) * Cc + ch);
        acc.x += sv[v] * pv.x; acc.y += sv[v] * pv.y;
        acc.z += sv[v] * pv.z; acc.w += sv[v] * pv.w;
    }
    if (last) {
        *(float4*)(OutC + (size_t)bn * Cc + ch) = acc;
        if (threadIdx.x == 0) {
            float ent = 0.f;
#pragma unroll
            for (int v = 0; v < Vv; v++) ent -= sv[v] * logf(sv[v] + 1e-8f);
            Rout[bn] = 1.0f - ent / logf((float)Vv);
        }
    } else {
        union { uint16_t u[4]; uint2 p; } hh, ll;
        split1(acc.x, hh.u[0], ll.u[0]);
        split1(acc.y, hh.u[1], ll.u[1]);
        split1(acc.z, hh.u[2], ll.u[2]);
        split1(acc.w, hh.u[3], ll.u[3]);
        size_t o = (size_t)bn * Cc + ch;
        *(uint2*)(g_ch + o) = hh.p;
        *(uint2*)(g_cl + o) = ll.p;
    }
}

// ---------------------------------------------------------------------------
// Launch
// ---------------------------------------------------------------------------
extern "C" void kernel_launch(void* const* d_in, const int* in_sizes, int n_in,
                              void* d_out, int out_size) {
    const float* x       = (const float*)d_in[0];
    const float* w_views = (const float*)d_in[1];
    const float* w1      = (const float*)d_in[2];
    const float* b1      = (const float*)d_in[3];
    const float* w2      = (const float*)d_in[4];
    const float* b2      = (const float*)d_in[5];
    float* out = (float*)d_out;   // c [B,N,C] then r [B,N]

    float *P, *XW1, *CW1, *S;
    __nv_bfloat16 *xh, *xl, *ch, *cl, *Wh, *Wl;
    cudaGetSymbolAddress((void**)&P,   g_P);
    cudaGetSymbolAddress((void**)&XW1, g_XW1);
    cudaGetSymbolAddress((void**)&CW1, g_CW1);
    cudaGetSymbolAddress((void**)&S,   g_S);
    cudaGetSymbolAddress((void**)&xh,  g_xh);
    cudaGetSymbolAddress((void**)&xl,  g_xl);
    cudaGetSymbolAddress((void**)&ch,  g_ch);
    cudaGetSymbolAddress((void**)&cl,  g_cl);
    cudaGetSymbolAddress((void**)&Wh,  g_Wh);
    cudaGetSymbolAddress((void**)&Wl,  g_Wl);

    cudaFuncSetAttribute(mma_gemm<0>, cudaFuncAttributeMaxDynamicSharedMemorySize, SMEM_TOTAL);
    cudaFuncSetAttribute(mma_gemm<1>, cudaFuncAttributeMaxDynamicSharedMemorySize, SMEM_TOTAL);

    // conversions
    {
        size_t tot = (size_t)BVN * Cc / 4;
        split_x_kernel<<<(unsigned)((tot + 255) / 256), 256>>>(x);
        size_t tw = (size_t)7 * WMAT;
        split_w_kernel<<<(unsigned)((tw + 255) / 256), 256>>>(w_views, w1);
        int tm = BN_ROWS * (Cc / 4);
        mean_kernel<<<(tm + 255) / 256, 256>>>(x);
    }
    // proj_x = x @ w_views (per view)
    {
        dim3 grid(Cc / 128, BN_ROWS / 128, Vv);   // (6, 49, 5)
        mma_gemm<1><<<grid, 256, SMEM_TOTAL>>>(xh, xl, Wh, Wl, P);
    }
    // XW1 = x @ w1[:C]
    {
        dim3 grid(Hh / 128, BVN / 128, 1);        // (6, 245)
        mma_gemm<0><<<grid, 256, SMEM_TOTAL>>>(xh, xl, Wh + (size_t)5 * WMAT, Wl + (size_t)5 * WMAT, XW1);
    }
    // iterations
    for (int it = 0; it < NUM_ITERS; it++) {
        dim3 gridc(Hh / 128, BN_ROWS / 128, 1);   // (6, 49)
        mma_gemm<0><<<gridc, 256, SMEM_TOTAL>>>(ch, cl, Wh + (size_t)6 * WMAT, Wl + (size_t)6 * WMAT, CW1);

        int blocks = (BVN * 32 + 255) / 256;
        score_kernel<<<blocks, 256>>>(XW1, CW1, b1, w2, b2, S);

        int last = (it == NUM_ITERS - 1) ? 1 : 0;
        float* rdst = out + (size_t)BN_ROWS * Cc;
        update_kernel<<<BN_ROWS, 192>>>(S, P, out, rdst, last);
    }
    (void)in_sizes; (void)n_in; (void)out_size;
}